// round 15
// baseline (speedup 1.0000x reference)
#include <cuda_runtime.h>
#include <math.h>

#define N_FEAT 7
#define FUZZ   2187
#define MID    512
#define NCLS   10
#define BATCH  4096
#define T21    21
#define CHUNK_K 9
#define NCHUNK 243           // 243*9 = 2187 k's
#define CT5    5             // 512-wide column tiles (2 streams of 256)
#define WCH    16            // j-chunks for W23 partials
#define SN     (T21 * FUZZ)  // 45927
#define GN     (NCLS * T21)  // 210
#define ZTOT   (SN + GN + NCLS)

// ---- device scratch (no allocations allowed) ----
__device__ float g_S[SN];    // zero-init at load; re-zeroed by k_main trailer
__device__ float g_rowS[T21];
__device__ float g_partW[WCH * NCLS * MID];
__device__ float g_G[GN];    // accumulated atomically by k_fold
__device__ float g_q[NCLS];
__device__ float g_cc2[NCLS];

// ============================================================
// Stage 1: digit-factorized wei reduction -> atomic g_S.
//   CHUNK_K=9: digits f0..f4 block-constant (5 scalar slots),
//   f5/f6 compile-time. ST=2 column streams. 1215 S-blocks
//   (8.2/SM) + 32 tail blocks for W23 partials.
// ============================================================
__global__ void __launch_bounds__(256) k_stage1(
        const float* __restrict__ wei,
        const float* __restrict__ W2,
        const float* __restrict__ W3) {
    int b   = blockIdx.x;
    int tid = threadIdx.x;

    if (b < NCHUNK * CT5) {
        int colTile = b % CT5;
        int chunk   = b / CT5;
        int jA = colTile * 512 + tid;
        int jB = jA + 256;
        bool okA = (jA < FUZZ), okB = (jB < FUZZ);
        int ja = okA ? jA : 0, jb = okB ? jB : 0;

        float aA[11], aB[11];
#pragma unroll
        for (int s = 0; s < 11; s++) { aA[s] = 0.f; aB[s] = 0.f; }

        const float* base = wei + (size_t)chunk * CHUNK_K * 7 * FUZZ;
#pragma unroll
        for (int q = 0; q < CHUNK_K; q++) {
            const float* rp = base + (size_t)q * 7 * FUZZ;
#pragma unroll
            for (int f = 0; f < 5; f++) {
                aA[f] += __ldg(rp + f * FUZZ + ja);
                aB[f] += __ldg(rp + f * FUZZ + jb);
            }
            // f5 digit = q/3, f6 digit = q%3 (compile-time under unroll)
            aA[5 + q / 3] += __ldg(rp + 5 * FUZZ + ja);
            aB[5 + q / 3] += __ldg(rp + 5 * FUZZ + jb);
            aA[8 + q % 3] += __ldg(rp + 6 * FUZZ + ja);
            aB[8 + q % 3] += __ldg(rp + 6 * FUZZ + jb);
        }

        int t0 = 0  + (chunk / 81) % 3;
        int t1 = 3  + (chunk / 27) % 3;
        int t2 = 6  + (chunk / 9) % 3;
        int t3 = 9  + (chunk / 3) % 3;
        int t4 = 12 + chunk % 3;
        if (okA) {
            atomicAdd(&g_S[t0 * FUZZ + jA], aA[0]);
            atomicAdd(&g_S[t1 * FUZZ + jA], aA[1]);
            atomicAdd(&g_S[t2 * FUZZ + jA], aA[2]);
            atomicAdd(&g_S[t3 * FUZZ + jA], aA[3]);
            atomicAdd(&g_S[t4 * FUZZ + jA], aA[4]);
#pragma unroll
            for (int m = 0; m < 3; m++) {
                atomicAdd(&g_S[(15 + m) * FUZZ + jA], aA[5 + m]);
                atomicAdd(&g_S[(18 + m) * FUZZ + jA], aA[8 + m]);
            }
        }
        if (okB) {
            atomicAdd(&g_S[t0 * FUZZ + jB], aB[0]);
            atomicAdd(&g_S[t1 * FUZZ + jB], aB[1]);
            atomicAdd(&g_S[t2 * FUZZ + jB], aB[2]);
            atomicAdd(&g_S[t3 * FUZZ + jB], aB[3]);
            atomicAdd(&g_S[t4 * FUZZ + jB], aB[4]);
#pragma unroll
            for (int m = 0; m < 3; m++) {
                atomicAdd(&g_S[(15 + m) * FUZZ + jB], aB[5 + m]);
                atomicAdd(&g_S[(18 + m) * FUZZ + jB], aB[8 + m]);
            }
        }
    } else {
        // ---- W23 partial: W23[n,i] = sum_j W3[n,j] * W2[j,i] ----
        int b2    = b - NCHUNK * CT5;
        int itile = b2 & 1;
        int chunk = b2 >> 1;
        int i  = itile * 256 + tid;
        int j0 = chunk * 137;
        int j1 = min(FUZZ, j0 + 137);

        float acc[NCLS];
#pragma unroll
        for (int n = 0; n < NCLS; n++) acc[n] = 0.f;
        for (int j = j0; j < j1; j++) {
            float w2 = __ldg(W2 + j * MID + i);
#pragma unroll
            for (int n = 0; n < NCLS; n++)
                acc[n] += __ldg(W3 + n * FUZZ + j) * w2;
        }
#pragma unroll
        for (int n = 0; n < NCLS; n++)
            g_partW[chunk * (NCLS * MID) + n * MID + i] = acc[n];
    }
}

// ============================================================
// Stage 2: fold + contract fused.
//   Blocks 0..35 (9 j-tiles x 4 i-slices): partial
//   V[n,j] = (isl==0 ? W3[n,j] : 0) + sum_{i in slice} W23[n,i] W1[i,j],
//   then contract partial V against S -> atomicAdd g_G, g_q.
//   Block 36: rowS. Block 37: cc2.
// ============================================================
__global__ void __launch_bounds__(256) k_fold(const float* __restrict__ W1,
                                              const float* __restrict__ W3,
                                              const float* __restrict__ b1,
                                              const float* __restrict__ b2,
                                              const float* __restrict__ b3) {
    int b = blockIdx.x, tid = threadIdx.x, lane = tid & 31, warp = tid >> 5;

    if (b < 36) {
        __shared__ float sW[NCLS * 128];
        __shared__ float sV[NCLS * 256];
        int jt = b % 9, isl = b / 9;
        int i0 = isl * 128;

        for (int e = tid; e < NCLS * 128; e += 256) {
            int n = e / 128, il = e % 128;
            float s = 0.f;
#pragma unroll
            for (int c = 0; c < WCH; c++)
                s += g_partW[c * (NCLS * MID) + n * MID + i0 + il];
            sW[e] = s;
        }
        __syncthreads();

        int j = jt * 256 + tid;
        bool ok = (j < FUZZ);
        int jj = ok ? j : 0;

        float V[NCLS];
#pragma unroll
        for (int n = 0; n < NCLS; n++) V[n] = 0.f;
#pragma unroll 4
        for (int il = 0; il < 128; il++) {
            float w1 = __ldg(W1 + (size_t)(i0 + il) * FUZZ + jj);
#pragma unroll
            for (int n = 0; n < NCLS; n++)
                V[n] += sW[n * 128 + il] * w1;
        }
#pragma unroll
        for (int n = 0; n < NCLS; n++) {
            float v = V[n] + ((isl == 0) ? __ldg(W3 + n * FUZZ + jj) : 0.f);
            sV[n * 256 + tid] = ok ? v : 0.f;
        }
        __syncthreads();

        // contract: 210 G-dots + 10 q-dots over this block's 256 j's
        int j0 = jt * 256;
        for (int d = warp; d < GN + NCLS; d += 8) {
            float s = 0.f;
            if (d < GN) {
                int n = d / T21, t = d % T21;
                const float* Sv = g_S + t * FUZZ;
#pragma unroll
                for (int c = 0; c < 8; c++) {
                    int idx = c * 32 + lane;
                    int jx = j0 + idx;
                    float Sval = (jx < FUZZ) ? __ldg(Sv + jx) : 0.f;
                    s += sV[n * 256 + idx] * Sval;
                }
            } else {
                int n = d - GN;
#pragma unroll
                for (int c = 0; c < 8; c++)
                    s += sV[n * 256 + c * 32 + lane];
            }
            for (int o = 16; o; o >>= 1)
                s += __shfl_down_sync(0xffffffffu, s, o);
            if (lane == 0) {
                if (d < GN) atomicAdd(&g_G[d], s);
                else        atomicAdd(&g_q[d - GN], s);
            }
        }
    } else if (b == 36) {
        // rowS[t] = sum_j S[t,j]  (warp per t, looping)
        for (int t = warp; t < T21; t += 8) {
            float s = 0.f;
            const float* Sp = g_S + t * FUZZ;
            for (int j = lane; j < FUZZ; j += 32) s += Sp[j];
            for (int o = 16; o; o >>= 1)
                s += __shfl_down_sync(0xffffffffu, s, o);
            if (lane == 0) g_rowS[t] = s;
        }
    } else {
        // cc2[n] = W3[n].b2 + b3[n] + W23[n].b1
        for (int n = warp; n < NCLS; n += 8) {
            float s = 0.f;
            for (int j = lane; j < FUZZ; j += 32)
                s += __ldg(W3 + n * FUZZ + j) * __ldg(b2 + j);
            for (int e = lane; e < WCH * MID; e += 32) {
                int c = e / MID, i = e % MID;
                s += g_partW[c * (NCLS * MID) + n * MID + i] * __ldg(b1 + i);
            }
            for (int o = 16; o; o >>= 1)
                s += __shfl_down_sync(0xffffffffu, s, o);
            if (lane == 0) g_cc2[n] = s + __ldg(b3 + n);
        }
    }
}

// ============================================================
// Stage 3: one thread per batch row; trailer re-zeros g_S/g_G/g_q
// so the next call (graph replay) starts clean.
// ============================================================
__global__ void __launch_bounds__(256) k_main(
        const float* __restrict__ x,  const float* __restrict__ cc,
        const float* __restrict__ bb, const float* __restrict__ bais,
        float* __restrict__ out) {
    __shared__ float sG[GN];
    __shared__ float sq[NCLS];
    __shared__ float scc[NCLS];
    __shared__ float srowS[T21];
    __shared__ float sc[T21];
    __shared__ float sib[T21];

    int tid = threadIdx.x;
    if (tid < GN) sG[tid] = g_G[tid];
    if (tid < NCLS) { sq[tid] = g_q[tid]; scc[tid] = g_cc2[tid]; }
    if (tid < T21) {
        srowS[tid] = g_rowS[tid];
        sc[tid] = __ldg(cc + tid);
        float bw = __ldg(bb + tid);
        sib[tid] = 1.0f / (bw * bw);
    }
    float bv = __ldg(bais);
    __syncthreads();

    int row = blockIdx.x * 256 + tid;
    float xv[N_FEAT];
#pragma unroll
    for (int f = 0; f < N_FEAT; f++) xv[f] = __ldg(x + row * N_FEAT + f);

    float u[T21];
    float rs = (float)FUZZ * bv;
#pragma unroll
    for (int t = 0; t < T21; t++) {
        float d = xv[t / 3] - sc[t];
        u[t] = expf(-d * d * sib[t]);
        rs += u[t] * srowS[t];
    }
    float inv = 1.0f / rs;

#pragma unroll
    for (int n = 0; n < NCLS; n++) {
        float s = bv * sq[n];
#pragma unroll
        for (int t = 0; t < T21; t++) s += u[t] * sG[n * T21 + t];
        float h = inv * s + scc[n];
        out[row * NCLS + n] = (h >= 0.f) ? h : 0.2f * h;
    }

    // ---- trailer: zero accumulators for the next call ----
    int gtid = blockIdx.x * 256 + tid;       // 0..4095
    for (int i = gtid; i < ZTOT; i += BATCH) {
        if (i < SN)           g_S[i] = 0.f;
        else if (i < SN + GN) g_G[i - SN] = 0.f;
        else                  g_q[i - SN - GN] = 0.f;
    }
}

// ============================================================
extern "C" void kernel_launch(void* const* d_in, const int* in_sizes, int n_in,
                              void* d_out, int out_size) {
    const float* x    = (const float*)d_in[0];
    const float* c    = (const float*)d_in[1];
    const float* b    = (const float*)d_in[2];
    const float* wei  = (const float*)d_in[3];
    const float* bais = (const float*)d_in[4];
    const float* W1   = (const float*)d_in[5];
    const float* b1   = (const float*)d_in[6];
    const float* W2   = (const float*)d_in[7];
    const float* b2   = (const float*)d_in[8];
    const float* W3   = (const float*)d_in[9];
    const float* b3   = (const float*)d_in[10];
    float* out = (float*)d_out;

    k_stage1<<<NCHUNK * CT5 + 2 * WCH, 256>>>(wei, W2, W3);
    k_fold<<<38, 256>>>(W1, W3, b1, b2, b3);
    k_main<<<BATCH / 256, 256>>>(x, c, b, bais, out);
}

// round 16
// speedup vs baseline: 1.1215x; 1.1215x over previous
#include <cuda_runtime.h>
#include <math.h>

#define N_FEAT 7
#define FUZZ   2187
#define MID    512
#define NCLS   10
#define BATCH  4096
#define T21    21
#define NCHUNK 81            // chunks of 27 k  (measured-best)
#define CHUNK_K 27
#define CT5    5             // 512-wide column tiles (2 streams of 256)
#define WCH    16            // j-chunks for W23 partials
#define SN     (T21 * FUZZ)  // 45927
#define GN     (NCLS * T21)  // 210
#define ZTOT   (SN + GN + NCLS)

// ---- device scratch (no allocations allowed) ----
__device__ float g_S[SN];    // zero-init at load; re-zeroed by k_main trailer
__device__ float g_rowS[T21];
__device__ float g_partW[WCH * NCLS * MID];
__device__ float g_G[GN];    // accumulated atomically by k_fold
__device__ float g_q[NCLS];
__device__ float g_cc2[NCLS];

// ============================================================
// Stage 1 (R12 measured-best, verbatim): digit-factorized wei
//   reduction -> atomic g_S. TWO j-column streams per thread.
//   + 32 tail blocks: W23 partials.
// ============================================================
__global__ void __launch_bounds__(256) k_stage1(
        const float* __restrict__ wei,
        const float* __restrict__ W2,
        const float* __restrict__ W3) {
    int b   = blockIdx.x;
    int tid = threadIdx.x;

    if (b < NCHUNK * CT5) {
        int colTile = b % CT5;
        int chunk   = b / CT5;
        int jA = colTile * 512 + tid;
        int jB = jA + 256;
        bool okA = (jA < FUZZ), okB = (jB < FUZZ);
        int ja = okA ? jA : 0, jb = okB ? jB : 0;

        float aA[13], aB[13];
#pragma unroll
        for (int s = 0; s < 13; s++) { aA[s] = 0.f; aB[s] = 0.f; }

        const float* base = wei + (size_t)chunk * CHUNK_K * 7 * FUZZ;
#pragma unroll 3
        for (int kk = 0; kk < CHUNK_K; kk++) {
            const float* rp = base + (size_t)kk * 7 * FUZZ;
            int m4 = kk / 9, m5 = (kk / 3) % 3, m6 = kk % 3;
#pragma unroll
            for (int f = 0; f < 4; f++) {
                aA[f] += __ldg(rp + f * FUZZ + ja);
                aB[f] += __ldg(rp + f * FUZZ + jb);
            }
            float v4A = __ldg(rp + 4 * FUZZ + ja), v4B = __ldg(rp + 4 * FUZZ + jb);
            float v5A = __ldg(rp + 5 * FUZZ + ja), v5B = __ldg(rp + 5 * FUZZ + jb);
            float v6A = __ldg(rp + 6 * FUZZ + ja), v6B = __ldg(rp + 6 * FUZZ + jb);
#pragma unroll
            for (int m = 0; m < 3; m++) {
                aA[4 + m]  += (m4 == m) ? v4A : 0.f;
                aB[4 + m]  += (m4 == m) ? v4B : 0.f;
                aA[7 + m]  += (m5 == m) ? v5A : 0.f;
                aB[7 + m]  += (m5 == m) ? v5B : 0.f;
                aA[10 + m] += (m6 == m) ? v6A : 0.f;
                aB[10 + m] += (m6 == m) ? v6B : 0.f;
            }
        }

        int t0 = (chunk / 27) % 3;
        int t1 = (chunk / 9) % 3;
        int t2 = (chunk / 3) % 3;
        int t3 = chunk % 3;
        if (okA) {
            atomicAdd(&g_S[(0 + t0) * FUZZ + jA], aA[0]);
            atomicAdd(&g_S[(3 + t1) * FUZZ + jA], aA[1]);
            atomicAdd(&g_S[(6 + t2) * FUZZ + jA], aA[2]);
            atomicAdd(&g_S[(9 + t3) * FUZZ + jA], aA[3]);
#pragma unroll
            for (int m = 0; m < 3; m++) {
                atomicAdd(&g_S[(12 + m) * FUZZ + jA], aA[4 + m]);
                atomicAdd(&g_S[(15 + m) * FUZZ + jA], aA[7 + m]);
                atomicAdd(&g_S[(18 + m) * FUZZ + jA], aA[10 + m]);
            }
        }
        if (okB) {
            atomicAdd(&g_S[(0 + t0) * FUZZ + jB], aB[0]);
            atomicAdd(&g_S[(3 + t1) * FUZZ + jB], aB[1]);
            atomicAdd(&g_S[(6 + t2) * FUZZ + jB], aB[2]);
            atomicAdd(&g_S[(9 + t3) * FUZZ + jB], aB[3]);
#pragma unroll
            for (int m = 0; m < 3; m++) {
                atomicAdd(&g_S[(12 + m) * FUZZ + jB], aB[4 + m]);
                atomicAdd(&g_S[(15 + m) * FUZZ + jB], aB[7 + m]);
                atomicAdd(&g_S[(18 + m) * FUZZ + jB], aB[10 + m]);
            }
        }
    } else {
        // ---- W23 partial: W23[n,i] = sum_j W3[n,j] * W2[j,i] ----
        int b2    = b - NCHUNK * CT5;
        int itile = b2 & 1;
        int chunk = b2 >> 1;
        int i  = itile * 256 + tid;
        int j0 = chunk * 137;
        int j1 = min(FUZZ, j0 + 137);

        float acc[NCLS];
#pragma unroll
        for (int n = 0; n < NCLS; n++) acc[n] = 0.f;
        for (int j = j0; j < j1; j++) {
            float w2 = __ldg(W2 + j * MID + i);
#pragma unroll
            for (int n = 0; n < NCLS; n++)
                acc[n] += __ldg(W3 + n * FUZZ + j) * w2;
        }
#pragma unroll
        for (int n = 0; n < NCLS; n++)
            g_partW[chunk * (NCLS * MID) + n * MID + i] = acc[n];
    }
}

// ============================================================
// Stage 2 (R15's merged fold, verbatim): blocks 0..35 compute
//   partial V and contract against S -> atomic g_G/g_q;
//   block 36: rowS; block 37: cc2.
// ============================================================
__global__ void __launch_bounds__(256) k_fold(const float* __restrict__ W1,
                                              const float* __restrict__ W3,
                                              const float* __restrict__ b1,
                                              const float* __restrict__ b2,
                                              const float* __restrict__ b3) {
    int b = blockIdx.x, tid = threadIdx.x, lane = tid & 31, warp = tid >> 5;

    if (b < 36) {
        __shared__ float sW[NCLS * 128];
        __shared__ float sV[NCLS * 256];
        int jt = b % 9, isl = b / 9;
        int i0 = isl * 128;

        for (int e = tid; e < NCLS * 128; e += 256) {
            int n = e / 128, il = e % 128;
            float s = 0.f;
#pragma unroll
            for (int c = 0; c < WCH; c++)
                s += g_partW[c * (NCLS * MID) + n * MID + i0 + il];
            sW[e] = s;
        }
        __syncthreads();

        int j = jt * 256 + tid;
        bool ok = (j < FUZZ);
        int jj = ok ? j : 0;

        float V[NCLS];
#pragma unroll
        for (int n = 0; n < NCLS; n++) V[n] = 0.f;
#pragma unroll 4
        for (int il = 0; il < 128; il++) {
            float w1 = __ldg(W1 + (size_t)(i0 + il) * FUZZ + jj);
#pragma unroll
            for (int n = 0; n < NCLS; n++)
                V[n] += sW[n * 128 + il] * w1;
        }
#pragma unroll
        for (int n = 0; n < NCLS; n++) {
            float v = V[n] + ((isl == 0) ? __ldg(W3 + n * FUZZ + jj) : 0.f);
            sV[n * 256 + tid] = ok ? v : 0.f;
        }
        __syncthreads();

        int j0 = jt * 256;
        for (int d = warp; d < GN + NCLS; d += 8) {
            float s = 0.f;
            if (d < GN) {
                int n = d / T21, t = d % T21;
                const float* Sv = g_S + t * FUZZ;
#pragma unroll
                for (int c = 0; c < 8; c++) {
                    int idx = c * 32 + lane;
                    int jx = j0 + idx;
                    float Sval = (jx < FUZZ) ? __ldg(Sv + jx) : 0.f;
                    s += sV[n * 256 + idx] * Sval;
                }
            } else {
                int n = d - GN;
#pragma unroll
                for (int c = 0; c < 8; c++)
                    s += sV[n * 256 + c * 32 + lane];
            }
            for (int o = 16; o; o >>= 1)
                s += __shfl_down_sync(0xffffffffu, s, o);
            if (lane == 0) {
                if (d < GN) atomicAdd(&g_G[d], s);
                else        atomicAdd(&g_q[d - GN], s);
            }
        }
    } else if (b == 36) {
        for (int t = warp; t < T21; t += 8) {
            float s = 0.f;
            const float* Sp = g_S + t * FUZZ;
            for (int j = lane; j < FUZZ; j += 32) s += Sp[j];
            for (int o = 16; o; o >>= 1)
                s += __shfl_down_sync(0xffffffffu, s, o);
            if (lane == 0) g_rowS[t] = s;
        }
    } else {
        for (int n = warp; n < NCLS; n += 8) {
            float s = 0.f;
            for (int j = lane; j < FUZZ; j += 32)
                s += __ldg(W3 + n * FUZZ + j) * __ldg(b2 + j);
            for (int e = lane; e < WCH * MID; e += 32) {
                int c = e / MID, i = e % MID;
                s += g_partW[c * (NCLS * MID) + n * MID + i] * __ldg(b1 + i);
            }
            for (int o = 16; o; o >>= 1)
                s += __shfl_down_sync(0xffffffffu, s, o);
            if (lane == 0) g_cc2[n] = s + __ldg(b3 + n);
        }
    }
}

// ============================================================
// Stage 3: one thread per batch row; trailer re-zeros g_S/g_G/g_q
// ============================================================
__global__ void __launch_bounds__(256) k_main(
        const float* __restrict__ x,  const float* __restrict__ cc,
        const float* __restrict__ bb, const float* __restrict__ bais,
        float* __restrict__ out) {
    __shared__ float sG[GN];
    __shared__ float sq[NCLS];
    __shared__ float scc[NCLS];
    __shared__ float srowS[T21];
    __shared__ float sc[T21];
    __shared__ float sib[T21];

    int tid = threadIdx.x;
    if (tid < GN) sG[tid] = g_G[tid];
    if (tid < NCLS) { sq[tid] = g_q[tid]; scc[tid] = g_cc2[tid]; }
    if (tid < T21) {
        srowS[tid] = g_rowS[tid];
        sc[tid] = __ldg(cc + tid);
        float bw = __ldg(bb + tid);
        sib[tid] = 1.0f / (bw * bw);
    }
    float bv = __ldg(bais);
    __syncthreads();

    int row = blockIdx.x * 256 + tid;
    float xv[N_FEAT];
#pragma unroll
    for (int f = 0; f < N_FEAT; f++) xv[f] = __ldg(x + row * N_FEAT + f);

    float u[T21];
    float rs = (float)FUZZ * bv;
#pragma unroll
    for (int t = 0; t < T21; t++) {
        float d = xv[t / 3] - sc[t];
        u[t] = expf(-d * d * sib[t]);
        rs += u[t] * srowS[t];
    }
    float inv = 1.0f / rs;

#pragma unroll
    for (int n = 0; n < NCLS; n++) {
        float s = bv * sq[n];
#pragma unroll
        for (int t = 0; t < T21; t++) s += u[t] * sG[n * T21 + t];
        float h = inv * s + scc[n];
        out[row * NCLS + n] = (h >= 0.f) ? h : 0.2f * h;
    }

    // ---- trailer: zero accumulators for the next call ----
    int gtid = blockIdx.x * 256 + tid;       // 0..4095
    for (int i = gtid; i < ZTOT; i += BATCH) {
        if (i < SN)           g_S[i] = 0.f;
        else if (i < SN + GN) g_G[i - SN] = 0.f;
        else                  g_q[i - SN - GN] = 0.f;
    }
}

// ============================================================
extern "C" void kernel_launch(void* const* d_in, const int* in_sizes, int n_in,
                              void* d_out, int out_size) {
    const float* x    = (const float*)d_in[0];
    const float* c    = (const float*)d_in[1];
    const float* b    = (const float*)d_in[2];
    const float* wei  = (const float*)d_in[3];
    const float* bais = (const float*)d_in[4];
    const float* W1   = (const float*)d_in[5];
    const float* b1   = (const float*)d_in[6];
    const float* W2   = (const float*)d_in[7];
    const float* b2   = (const float*)d_in[8];
    const float* W3   = (const float*)d_in[9];
    const float* b3   = (const float*)d_in[10];
    float* out = (float*)d_out;

    k_stage1<<<NCHUNK * CT5 + 2 * WCH, 256>>>(wei, W2, W3);
    k_fold<<<38, 256>>>(W1, W3, b1, b2, b3);
    k_main<<<BATCH / 256, 256>>>(x, c, b, bais, out);
}

// round 17
// speedup vs baseline: 1.1957x; 1.0661x over previous
#include <cuda_runtime.h>
#include <math.h>

#define N_FEAT 7
#define FUZZ   2187
#define MID    512
#define NCLS   10
#define BATCH  4096
#define T21    21
#define NCHUNK 81            // chunks of 27 k  (measured-best)
#define CHUNK_K 27
#define CT5    5             // 512-wide column tiles (2 streams of 256)
#define WCH    16            // j-chunks for W23 partials
#define ISL    16            // i-slices in k_fold
#define ISZ    (MID / ISL)   // 32
#define SN     (T21 * FUZZ)  // 45927
#define GN     (NCLS * T21)  // 210
#define ZTOT   (SN + GN + NCLS)

// ---- device scratch (no allocations allowed) ----
__device__ float g_S[SN];    // zero-init at load; re-zeroed by k_main trailer
__device__ float g_rowS[T21];
__device__ float g_partW[WCH * NCLS * MID];
__device__ float g_G[GN];    // accumulated atomically by k_fold
__device__ float g_q[NCLS];
__device__ float g_cc2[NCLS];

// ============================================================
// Stage 1 (measured-best, FROZEN): digit-factorized wei
//   reduction -> atomic g_S. TWO j-column streams per thread.
//   + 32 tail blocks: W23 partials.
// ============================================================
__global__ void __launch_bounds__(256) k_stage1(
        const float* __restrict__ wei,
        const float* __restrict__ W2,
        const float* __restrict__ W3) {
    int b   = blockIdx.x;
    int tid = threadIdx.x;

    if (b < NCHUNK * CT5) {
        int colTile = b % CT5;
        int chunk   = b / CT5;
        int jA = colTile * 512 + tid;
        int jB = jA + 256;
        bool okA = (jA < FUZZ), okB = (jB < FUZZ);
        int ja = okA ? jA : 0, jb = okB ? jB : 0;

        float aA[13], aB[13];
#pragma unroll
        for (int s = 0; s < 13; s++) { aA[s] = 0.f; aB[s] = 0.f; }

        const float* base = wei + (size_t)chunk * CHUNK_K * 7 * FUZZ;
#pragma unroll 3
        for (int kk = 0; kk < CHUNK_K; kk++) {
            const float* rp = base + (size_t)kk * 7 * FUZZ;
            int m4 = kk / 9, m5 = (kk / 3) % 3, m6 = kk % 3;
#pragma unroll
            for (int f = 0; f < 4; f++) {
                aA[f] += __ldg(rp + f * FUZZ + ja);
                aB[f] += __ldg(rp + f * FUZZ + jb);
            }
            float v4A = __ldg(rp + 4 * FUZZ + ja), v4B = __ldg(rp + 4 * FUZZ + jb);
            float v5A = __ldg(rp + 5 * FUZZ + ja), v5B = __ldg(rp + 5 * FUZZ + jb);
            float v6A = __ldg(rp + 6 * FUZZ + ja), v6B = __ldg(rp + 6 * FUZZ + jb);
#pragma unroll
            for (int m = 0; m < 3; m++) {
                aA[4 + m]  += (m4 == m) ? v4A : 0.f;
                aB[4 + m]  += (m4 == m) ? v4B : 0.f;
                aA[7 + m]  += (m5 == m) ? v5A : 0.f;
                aB[7 + m]  += (m5 == m) ? v5B : 0.f;
                aA[10 + m] += (m6 == m) ? v6A : 0.f;
                aB[10 + m] += (m6 == m) ? v6B : 0.f;
            }
        }

        int t0 = (chunk / 27) % 3;
        int t1 = (chunk / 9) % 3;
        int t2 = (chunk / 3) % 3;
        int t3 = chunk % 3;
        if (okA) {
            atomicAdd(&g_S[(0 + t0) * FUZZ + jA], aA[0]);
            atomicAdd(&g_S[(3 + t1) * FUZZ + jA], aA[1]);
            atomicAdd(&g_S[(6 + t2) * FUZZ + jA], aA[2]);
            atomicAdd(&g_S[(9 + t3) * FUZZ + jA], aA[3]);
#pragma unroll
            for (int m = 0; m < 3; m++) {
                atomicAdd(&g_S[(12 + m) * FUZZ + jA], aA[4 + m]);
                atomicAdd(&g_S[(15 + m) * FUZZ + jA], aA[7 + m]);
                atomicAdd(&g_S[(18 + m) * FUZZ + jA], aA[10 + m]);
            }
        }
        if (okB) {
            atomicAdd(&g_S[(0 + t0) * FUZZ + jB], aB[0]);
            atomicAdd(&g_S[(3 + t1) * FUZZ + jB], aB[1]);
            atomicAdd(&g_S[(6 + t2) * FUZZ + jB], aB[2]);
            atomicAdd(&g_S[(9 + t3) * FUZZ + jB], aB[3]);
#pragma unroll
            for (int m = 0; m < 3; m++) {
                atomicAdd(&g_S[(12 + m) * FUZZ + jB], aB[4 + m]);
                atomicAdd(&g_S[(15 + m) * FUZZ + jB], aB[7 + m]);
                atomicAdd(&g_S[(18 + m) * FUZZ + jB], aB[10 + m]);
            }
        }
    } else {
        // ---- W23 partial: W23[n,i] = sum_j W3[n,j] * W2[j,i] ----
        int b2    = b - NCHUNK * CT5;
        int itile = b2 & 1;
        int chunk = b2 >> 1;
        int i  = itile * 256 + tid;
        int j0 = chunk * 137;
        int j1 = min(FUZZ, j0 + 137);

        float acc[NCLS];
#pragma unroll
        for (int n = 0; n < NCLS; n++) acc[n] = 0.f;
        for (int j = j0; j < j1; j++) {
            float w2 = __ldg(W2 + j * MID + i);
#pragma unroll
            for (int n = 0; n < NCLS; n++)
                acc[n] += __ldg(W3 + n * FUZZ + j) * w2;
        }
#pragma unroll
        for (int n = 0; n < NCLS; n++)
            g_partW[chunk * (NCLS * MID) + n * MID + i] = acc[n];
    }
}

// ============================================================
// Stage 2: fold + contract. 144 V-blocks (9 j-tiles x 16 i-slices):
//   partial V[n,j] contracted against S -> atomic g_G/g_q.
//   Block 144: rowS. Block 145: cc2.
// ============================================================
__global__ void __launch_bounds__(256) k_fold(const float* __restrict__ W1,
                                              const float* __restrict__ W3,
                                              const float* __restrict__ b1,
                                              const float* __restrict__ b2,
                                              const float* __restrict__ b3) {
    int b = blockIdx.x, tid = threadIdx.x, lane = tid & 31, warp = tid >> 5;

    if (b < 9 * ISL) {
        __shared__ float sW[NCLS * ISZ];
        __shared__ float sV[NCLS * 256];
        int jt = b % 9, isl = b / 9;
        int i0 = isl * ISZ;

        for (int e = tid; e < NCLS * ISZ; e += 256) {
            int n = e / ISZ, il = e % ISZ;
            float s = 0.f;
#pragma unroll
            for (int c = 0; c < WCH; c++)
                s += g_partW[c * (NCLS * MID) + n * MID + i0 + il];
            sW[e] = s;
        }
        __syncthreads();

        int j = jt * 256 + tid;
        bool ok = (j < FUZZ);
        int jj = ok ? j : 0;

        float V[NCLS];
#pragma unroll
        for (int n = 0; n < NCLS; n++) V[n] = 0.f;
#pragma unroll 8
        for (int il = 0; il < ISZ; il++) {
            float w1 = __ldg(W1 + (size_t)(i0 + il) * FUZZ + jj);
#pragma unroll
            for (int n = 0; n < NCLS; n++)
                V[n] += sW[n * ISZ + il] * w1;
        }
#pragma unroll
        for (int n = 0; n < NCLS; n++) {
            float v = V[n] + ((isl == 0) ? __ldg(W3 + n * FUZZ + jj) : 0.f);
            sV[n * 256 + tid] = ok ? v : 0.f;
        }
        __syncthreads();

        int j0 = jt * 256;
        for (int d = warp; d < GN + NCLS; d += 8) {
            float s = 0.f;
            if (d < GN) {
                int n = d / T21, t = d % T21;
                const float* Sv = g_S + t * FUZZ;
#pragma unroll
                for (int c = 0; c < 8; c++) {
                    int idx = c * 32 + lane;
                    int jx = j0 + idx;
                    float Sval = (jx < FUZZ) ? __ldg(Sv + jx) : 0.f;
                    s += sV[n * 256 + idx] * Sval;
                }
            } else {
                int n = d - GN;
#pragma unroll
                for (int c = 0; c < 8; c++)
                    s += sV[n * 256 + c * 32 + lane];
            }
            for (int o = 16; o; o >>= 1)
                s += __shfl_down_sync(0xffffffffu, s, o);
            if (lane == 0) {
                if (d < GN) atomicAdd(&g_G[d], s);
                else        atomicAdd(&g_q[d - GN], s);
            }
        }
    } else if (b == 9 * ISL) {
        for (int t = warp; t < T21; t += 8) {
            float s = 0.f;
            const float* Sp = g_S + t * FUZZ;
            for (int j = lane; j < FUZZ; j += 32) s += Sp[j];
            for (int o = 16; o; o >>= 1)
                s += __shfl_down_sync(0xffffffffu, s, o);
            if (lane == 0) g_rowS[t] = s;
        }
    } else {
        for (int n = warp; n < NCLS; n += 8) {
            float s = 0.f;
            for (int j = lane; j < FUZZ; j += 32)
                s += __ldg(W3 + n * FUZZ + j) * __ldg(b2 + j);
            for (int e = lane; e < WCH * MID; e += 32) {
                int c = e / MID, i = e % MID;
                s += g_partW[c * (NCLS * MID) + n * MID + i] * __ldg(b1 + i);
            }
            for (int o = 16; o; o >>= 1)
                s += __shfl_down_sync(0xffffffffu, s, o);
            if (lane == 0) g_cc2[n] = s + __ldg(b3 + n);
        }
    }
}

// ============================================================
// Stage 3: 32 blocks x 128 threads, one thread per batch row,
//   __expf; trailer re-zeros g_S/g_G/g_q.
// ============================================================
__global__ void __launch_bounds__(128) k_main(
        const float* __restrict__ x,  const float* __restrict__ cc,
        const float* __restrict__ bb, const float* __restrict__ bais,
        float* __restrict__ out) {
    __shared__ float sG[GN];
    __shared__ float sq[NCLS];
    __shared__ float scc[NCLS];
    __shared__ float srowS[T21];
    __shared__ float sc[T21];
    __shared__ float sib[T21];

    int tid = threadIdx.x;
    for (int e = tid; e < GN; e += 128) sG[e] = g_G[e];
    if (tid < NCLS) { sq[tid] = g_q[tid]; scc[tid] = g_cc2[tid]; }
    if (tid < T21) {
        srowS[tid] = g_rowS[tid];
        sc[tid] = __ldg(cc + tid);
        float bw = __ldg(bb + tid);
        sib[tid] = 1.0f / (bw * bw);
    }
    float bv = __ldg(bais);
    __syncthreads();

    int row = blockIdx.x * 128 + tid;
    float xv[N_FEAT];
#pragma unroll
    for (int f = 0; f < N_FEAT; f++) xv[f] = __ldg(x + row * N_FEAT + f);

    float u[T21];
    float rs = (float)FUZZ * bv;
#pragma unroll
    for (int t = 0; t < T21; t++) {
        float d = xv[t / 3] - sc[t];
        u[t] = __expf(-d * d * sib[t]);
        rs += u[t] * srowS[t];
    }
    float inv = 1.0f / rs;

#pragma unroll
    for (int n = 0; n < NCLS; n++) {
        float s = bv * sq[n];
#pragma unroll
        for (int t = 0; t < T21; t++) s += u[t] * sG[n * T21 + t];
        float h = inv * s + scc[n];
        out[row * NCLS + n] = (h >= 0.f) ? h : 0.2f * h;
    }

    // ---- trailer: zero accumulators for the next call ----
    int gtid = blockIdx.x * 128 + tid;       // 0..4095
    for (int i = gtid; i < ZTOT; i += BATCH) {
        if (i < SN)           g_S[i] = 0.f;
        else if (i < SN + GN) g_G[i - SN] = 0.f;
        else                  g_q[i - SN - GN] = 0.f;
    }
}

// ============================================================
extern "C" void kernel_launch(void* const* d_in, const int* in_sizes, int n_in,
                              void* d_out, int out_size) {
    const float* x    = (const float*)d_in[0];
    const float* c    = (const float*)d_in[1];
    const float* b    = (const float*)d_in[2];
    const float* wei  = (const float*)d_in[3];
    const float* bais = (const float*)d_in[4];
    const float* W1   = (const float*)d_in[5];
    const float* b1   = (const float*)d_in[6];
    const float* W2   = (const float*)d_in[7];
    const float* b2   = (const float*)d_in[8];
    const float* W3   = (const float*)d_in[9];
    const float* b3   = (const float*)d_in[10];
    float* out = (float*)d_out;

    k_stage1<<<NCHUNK * CT5 + 2 * WCH, 256>>>(wei, W2, W3);
    k_fold<<<9 * ISL + 2, 256>>>(W1, W3, b1, b2, b3);
    k_main<<<BATCH / 128, 128>>>(x, c, b, bais, out);
}